// round 15
// baseline (speedup 1.0000x reference)
#include <cuda_runtime.h>
#include <cuda_fp16.h>
#include <math.h>
#include <cstdint>

// ---------------- problem constants ----------------
#define NUM_SUBNETS 8
#define REGIONS     50
#define TOTAL_R     400
#define HIDDEN      512
#define HEADS       8
#define HEAD_DIM    64
#define BATCH       256
#define FLAT        2500
#define ROWS        (NUM_SUBNETS * BATCH)   // 2048
#define LN_EPS      1e-5f
#define KPAD1       2560                    // FLAT padded to multiple of 64

// GEMM tiling: A single fp16, W single fp16.
#define BM 64
#define BN 64
#define BK 64
#define ASTRIDE 144                         // bytes per 64-col fp16 row (128 + 16 pad)
#define T_BYTES (BM * ASTRIDE)              // 9216 per tile array

// merged conversion kernel block ranges
#define NB_E  (ROWS * KPAD1 / 1024)         // 5120
#define NB_W1 (NUM_SUBNETS * (KPAD1 / 32) * (HIDDEN / 32))  // 10240
#define NB_W5 (13 * 256)                    // 3328
#define NB_ALL (NB_E + NB_W1 + NB_W5)       // 18688

typedef unsigned long long u64;

// ---------------- scratch (device globals) ----------------
__device__ __half g_flat[ROWS * KPAD1];
__device__ __half g_W1T_hi[NUM_SUBNETS * HIDDEN * KPAD1];
__device__ __half g_W2T_hi[NUM_SUBNETS * HIDDEN * HIDDEN];
__device__ __half g_WqkvT_hi[3 * HIDDEN * HIDDEN];
__device__ __half g_WoT_hi[HIDDEN * HIDDEN];
__device__ __half g_WpT_hi[HIDDEN * HIDDEN];

__device__ __half g_h  [ROWS * HIDDEN];
__device__ float  g_xsub[ROWS * HIDDEN];
__device__ __half g_xn [ROWS * HIDDEN];
__device__ __half g_q  [ROWS * HIDDEN];
__device__ __half g_k  [ROWS * HIDDEN];
__device__ __half g_v  [ROWS * HIDDEN];
__device__ __half g_ctx[ROWS * HIDDEN];
__device__ __half g_t  [ROWS * HIDDEN];

// ---------------- PTX helpers (sm_80-ratified only) ----------------
__device__ __forceinline__ uint32_t smem_u32(const void* p) {
    uint32_t a;
    asm("{ .reg .u64 t; cvta.to.shared.u64 t, %1; cvt.u32.u64 %0, t; }" : "=r"(a) : "l"(p));
    return a;
}
__device__ __forceinline__ void cpa16(uint32_t s, const void* g) {
    asm volatile("cp.async.cg.shared.global [%0], [%1], 16;" :: "r"(s), "l"(g));
}
__device__ __forceinline__ void cpa_commit() {
    asm volatile("cp.async.commit_group;" ::: "memory");
}
template<int N> __device__ __forceinline__ void cpa_wait() {
    asm volatile("cp.async.wait_group %0;" :: "n"(N) : "memory");
}
__device__ __forceinline__ void ldm4(uint32_t a, uint32_t* r) {
    asm volatile("ldmatrix.sync.aligned.m8n8.x4.shared.b16 {%0,%1,%2,%3}, [%4];"
        : "=r"(r[0]), "=r"(r[1]), "=r"(r[2]), "=r"(r[3]) : "r"(a));
}
__device__ __forceinline__ void mma16816(float* c, const uint32_t* a, uint32_t b0, uint32_t b1) {
    asm volatile("mma.sync.aligned.m16n8k16.row.col.f32.f16.f16.f32 "
        "{%0,%1,%2,%3},{%4,%5,%6,%7},{%8,%9},{%0,%1,%2,%3};"
        : "+f"(c[0]), "+f"(c[1]), "+f"(c[2]), "+f"(c[3])
        : "r"(a[0]), "r"(a[1]), "r"(a[2]), "r"(a[3]), "r"(b0), "r"(b1));
}

__device__ __forceinline__ void store_h2(__half* dst, size_t off, float v0, float v1) {
    *(__half2*)(dst + off) = __floats2half2_rn(v0, v1);
}

union H4 { uint2 u; __half2 p[2]; };

// ---------------- merged conversion kernel ----------------
struct W13 {
    const float* src[13];
    __half* dhi[13];
};

__global__ __launch_bounds__(256) void convert_all_kernel(
    const float* __restrict__ x, const float* __restrict__ W1, W13 wa)
{
    __shared__ float tile[32][33];
    const int tid = threadIdx.x;
    int id = blockIdx.x;

    if (id < NB_E) {
        int q = id * 256 + tid;
        int f0 = (q % (KPAD1 / 4)) * 4;
        int sb = q / (KPAD1 / 4);
        int b  = sb & (BATCH - 1);
        int s  = sb >> 8;
        const float* xb = x + (size_t)b * (TOTAL_R * TOTAL_R);
        float v[4];
        #pragma unroll
        for (int e = 0; e < 4; e++) {
            int f = f0 + e;
            float vv = 0.f;
            if (f < FLAT) {
                int i = f / REGIONS;
                int j = f - i * REGIONS;
                vv = xb[(s * REGIONS + i) * TOTAL_R + (s * REGIONS + j)];
            }
            v[e] = vv;
        }
        H4 hv;
        hv.p[0] = __floats2half2_rn(v[0], v[1]);
        hv.p[1] = __floats2half2_rn(v[2], v[3]);
        *(uint2*)(g_flat + (size_t)sb * KPAD1 + f0) = hv.u;
        return;
    }

    if (id < NB_E + NB_W1) {
        int id2 = id - NB_E;
        int z   = id2 / 1280;
        int rem = id2 % 1280;
        int k0  = (rem % 80) * 32;
        int n0  = (rem / 80) * 32;
        const float* sp = W1 + (size_t)z * FLAT * HIDDEN;
        {
            int row = tid >> 3, c4 = (tid & 7) * 4;
            int k = k0 + row;
            float4 vv = make_float4(0.f, 0.f, 0.f, 0.f);
            if (k < FLAT) vv = *(const float4*)(sp + (size_t)k * HIDDEN + n0 + c4);
            tile[row][c4]     = vv.x;
            tile[row][c4 + 1] = vv.y;
            tile[row][c4 + 2] = vv.z;
            tile[row][c4 + 3] = vv.w;
        }
        __syncthreads();
        int n = tid >> 3, kq = (tid & 7) * 4;
        H4 hv;
        hv.p[0] = __floats2half2_rn(tile[kq][n],     tile[kq + 1][n]);
        hv.p[1] = __floats2half2_rn(tile[kq + 2][n], tile[kq + 3][n]);
        size_t dbase = (size_t)z * HIDDEN * KPAD1;
        *(uint2*)(g_W1T_hi + dbase + (size_t)(n0 + n) * KPAD1 + k0 + kq) = hv.u;
        return;
    }

    {
        int id3 = id - NB_E - NB_W1;
        int z   = id3 >> 8;
        int rem = id3 & 255;
        int k0  = (rem & 15) * 32;
        int n0  = (rem >> 4) * 32;
        const float* sp = wa.src[z];
        __half* dhi = wa.dhi[z];
        {
            int row = tid >> 3, c4 = (tid & 7) * 4;
            float4 vv = *(const float4*)(sp + (size_t)(k0 + row) * HIDDEN + n0 + c4);
            tile[row][c4]     = vv.x;
            tile[row][c4 + 1] = vv.y;
            tile[row][c4 + 2] = vv.z;
            tile[row][c4 + 3] = vv.w;
        }
        __syncthreads();
        int n = tid >> 3, kq = (tid & 7) * 4;
        H4 hv;
        hv.p[0] = __floats2half2_rn(tile[kq][n],     tile[kq + 1][n]);
        hv.p[1] = __floats2half2_rn(tile[kq + 2][n], tile[kq + 3][n]);
        *(uint2*)(dhi + (size_t)(n0 + n) * HIDDEN + k0 + kq) = hv.u;
    }
}

// ---------------- mma.sync GEMM: C[2048][N] = A[2048][K] * W^T + epilogue ----------------
// C = A*W (both single fp16), fp32 accum. BM=BN=64, BK=64, 4-stage cp.async
// pipeline, 8 warps (wm 2)x(wn 2)x(wk 2), warp tile 32x32, K split across wk
// + SMEM reduce.
// EP: 0 relu->fp16 | 1 f32 | 2 qkv split fp16 | 3 fp16 | 4 resid+permute f32
template<int EP>
__global__ __launch_bounds__(256, 2) void tc_gemm(
    const __half* __restrict__ A, int sA,
    const __half* __restrict__ Bhi, int sB,
    long bSub, int Ksteps,
    const float* __restrict__ bias,
    float* __restrict__ o32,
    __half* __restrict__ oH,
    const float* __restrict__ resid,
    __half* __restrict__ oq, __half* __restrict__ okk, __half* __restrict__ ov,
    const float* __restrict__ bq, const float* __restrict__ bk, const float* __restrict__ bv)
{
    constexpr int NST = 4;
    constexpr uint32_t STG = 2 * T_BYTES;   // A + B
    extern __shared__ __align__(128) char smem[];
    const uint32_t sbase = smem_u32(smem);
    const int tid = threadIdx.x;
    const int mBase = blockIdx.y * BM;
    const int nBase = blockIdx.x * BN;
    const int sIdx = blockIdx.y >> 2;        // 4 M-tiles (256 rows) per subnet

    const __half* aP = A + (size_t)mBase * sA;
    size_t boff = (bSub > 0 ? (size_t)sIdx * (size_t)bSub : 0) + (size_t)nBase * sB;
    const __half* bH = Bhi + boff;
    const float* biasP = bias ? (bias + (bSub > 0 ? sIdx * HIDDEN : 0)) : bias;

    auto issue = [&](int chunk) {
        if (chunk < Ksteps) {
            const uint32_t st = sbase + (chunk % NST) * STG;
            const int k0 = chunk * BK;
            #pragma unroll
            for (int i = 0; i < 2; i++) {
                int idx = tid + i * 256;
                int row = idx >> 3, c = idx & 7;
                cpa16(st + row * ASTRIDE + c * 16, aP + (size_t)row * sA + k0 + c * 8);
                cpa16(st + T_BYTES + row * ASTRIDE + c * 16, bH + (size_t)row * sB + k0 + c * 8);
            }
        }
        cpa_commit();
    };

    issue(0); issue(1); issue(2);

    const int wid = tid >> 5, lane = tid & 31;
    const int wk = wid >> 2;
    const int wm = (wid >> 1) & 1;
    const int wn = wid & 1;
    const uint32_t lrow = lane & 15;
    const uint32_t lcol = (lane >> 4) * 16;

    float acc[2][4][4];
    #pragma unroll
    for (int i = 0; i < 2; i++)
        #pragma unroll
        for (int j = 0; j < 4; j++)
            #pragma unroll
            for (int t = 0; t < 4; t++) acc[i][j][t] = 0.f;

    for (int s = 0; s < Ksteps; ++s) {
        cpa_wait<2>();
        __syncthreads();
        issue(s + 3);
        const uint32_t st = sbase + (s % NST) * STG;
        #pragma unroll
        for (int j = 0; j < 2; ++j) {
            const int kk = wk * 2 + j;
            uint32_t aF[2][4], bF[2][4];
            #pragma unroll
            for (int am = 0; am < 2; am++) {
                uint32_t ad = st + (wm * 32 + am * 16 + lrow) * ASTRIDE + kk * 32 + lcol;
                ldm4(ad, aF[am]);
            }
            #pragma unroll
            for (int bt = 0; bt < 2; bt++) {
                uint32_t bd = st + T_BYTES + (wn * 32 + bt * 16 + lrow) * ASTRIDE + kk * 32 + lcol;
                ldm4(bd, bF[bt]);
            }
            #pragma unroll
            for (int am = 0; am < 2; am++)
                #pragma unroll
                for (int bt = 0; bt < 2; bt++) {
                    mma16816(acc[am][2*bt],   aF[am], bF[bt][0], bF[bt][2]);
                    mma16816(acc[am][2*bt+1], aF[am], bF[bt][1], bF[bt][3]);
                }
        }
    }

    // ---- reduce wk=1 partial sums into wk=0 via SMEM ----
    __syncthreads();
    float* red = (float*)smem;
    float* rbase = red + (wm * 2 + wn) * (32 * 34);
    if (wk == 1) {
        #pragma unroll
        for (int am = 0; am < 2; am++)
            #pragma unroll
            for (int an = 0; an < 4; an++)
                #pragma unroll
                for (int t = 0; t < 4; t++) {
                    int row = am * 16 + (lane >> 2) + (t >> 1) * 8;
                    int col = an * 8 + (lane & 3) * 2 + (t & 1);
                    rbase[row * 34 + col] = acc[am][an][t];
                }
    }
    __syncthreads();
    if (wk == 1) return;
    #pragma unroll
    for (int am = 0; am < 2; am++)
        #pragma unroll
        for (int an = 0; an < 4; an++)
            #pragma unroll
            for (int t = 0; t < 4; t++) {
                int row = am * 16 + (lane >> 2) + (t >> 1) * 8;
                int col = an * 8 + (lane & 3) * 2 + (t & 1);
                acc[am][an][t] += rbase[row * 34 + col];
            }

    // ---- epilogue (wk=0 warps only) ----
    #pragma unroll
    for (int am = 0; am < 2; am++) {
        #pragma unroll
        for (int an = 0; an < 4; an++) {
            int m0 = mBase + wm * 32 + am * 16 + (lane >> 2);
            int g  = nBase + wn * 32 + an * 8 + (lane & 3) * 2;
            #pragma unroll
            for (int half = 0; half < 2; half++) {
                int m = m0 + half * 8;
                float v0 = acc[am][an][half * 2];
                float v1 = acc[am][an][half * 2 + 1];
                if (EP == 0) {
                    v0 = fmaxf(v0 + biasP[g], 0.f);
                    v1 = fmaxf(v1 + biasP[g + 1], 0.f);
                    store_h2(oH, (size_t)m * HIDDEN + g, v0, v1);
                } else if (EP == 1) {
                    v0 += biasP[g]; v1 += biasP[g + 1];
                    *(float2*)(o32 + (size_t)m * HIDDEN + g) = make_float2(v0, v1);
                } else if (EP == 2) {
                    int which = g >> 9, lc = g & 511;
                    const float* bb = (which == 0) ? bq : (which == 1) ? bk : bv;
                    __half* dst = (which == 0) ? oq : (which == 1) ? okk : ov;
                    v0 += bb[lc]; v1 += bb[lc + 1];
                    store_h2(dst, (size_t)m * HIDDEN + lc, v0, v1);
                } else if (EP == 3) {
                    v0 += biasP[g]; v1 += biasP[g + 1];
                    store_h2(oH, (size_t)m * HIDDEN + g, v0, v1);
                } else {
                    v0 += biasP[g] + resid[(size_t)m * HIDDEN + g];
                    v1 += biasP[g + 1] + resid[(size_t)m * HIDDEN + g + 1];
                    int bb2 = m & (BATCH - 1), ss = m >> 8;
                    *(float2*)(o32 + ((size_t)((bb2 << 3) + ss)) * HIDDEN + g) = make_float2(v0, v1);
                }
            }
        }
    }
}

// ---------------- LayerNorm: one warp per row, xsub fp32 -> xn fp16 ----------------
__global__ __launch_bounds__(256) void ln_kernel(const float* __restrict__ lng,
                                                 const float* __restrict__ lnb)
{
    int gw = (blockIdx.x * 256 + threadIdx.x) >> 5;
    int l  = threadIdx.x & 31;
    if (gw >= ROWS) return;
    const float* xs = g_xsub + (size_t)gw * HIDDEN;

    float4 v[4];
    #pragma unroll
    for (int i = 0; i < 4; i++)
        v[i] = *(const float4*)(xs + l * 4 + i * 128);

    float s = 0.f, q = 0.f;
    #pragma unroll
    for (int i = 0; i < 4; i++) {
        s += v[i].x + v[i].y + v[i].z + v[i].w;
        q += v[i].x * v[i].x + v[i].y * v[i].y + v[i].z * v[i].z + v[i].w * v[i].w;
    }
    #pragma unroll
    for (int o = 16; o > 0; o >>= 1) {
        s += __shfl_xor_sync(0xFFFFFFFFu, s, o);
        q += __shfl_xor_sync(0xFFFFFFFFu, q, o);
    }
    float mean = s * (1.f / HIDDEN);
    float var  = q * (1.f / HIDDEN) - mean * mean;
    float inv  = rsqrtf(var + LN_EPS);

    __half* outp = g_xn + (size_t)gw * HIDDEN;
    #pragma unroll
    for (int i = 0; i < 4; i++) {
        int c = l * 4 + i * 128;
        float o0 = (v[i].x - mean) * inv * lng[c]     + lnb[c];
        float o1 = (v[i].y - mean) * inv * lng[c + 1] + lnb[c + 1];
        float o2 = (v[i].z - mean) * inv * lng[c + 2] + lnb[c + 2];
        float o3 = (v[i].w - mean) * inv * lng[c + 3] + lnb[c + 3];
        H4 hv;
        hv.p[0] = __floats2half2_rn(o0, o1);
        hv.p[1] = __floats2half2_rn(o2, o3);
        *(uint2*)(outp + c) = hv.u;
    }
}

// ---------------- attention: q,k,v fp16 -> ctx fp16 ----------------
__global__ __launch_bounds__(256) void attn_kernel()
{
    __shared__ float q_s[NUM_SUBNETS][520];
    __shared__ float k_s[NUM_SUBNETS][520];
    __shared__ float sc[HEADS][NUM_SUBNETS][NUM_SUBNETS];

    int b = blockIdx.x;
    int tid = threadIdx.x;

    for (int i = tid; i < NUM_SUBNETS * HIDDEN; i += 256) {
        int m = i >> 9, c = i & 511;
        size_t gi = ((size_t)(m * BATCH + b)) * HIDDEN + c;
        q_s[m][c] = __half2float(g_q[gi]);
        k_s[m][c] = __half2float(g_k[gi]);
    }
    __syncthreads();

    int h = tid >> 5, l = tid & 31;

    #pragma unroll
    for (int pp = 0; pp < 2; pp++) {
        int p = l + pp * 32;
        int m = p >> 3, n = p & 7;
        const float* qp = &q_s[m][h * HEAD_DIM];
        const float* kp = &k_s[n][h * HEAD_DIM];
        float sv = 0.f;
        #pragma unroll
        for (int d = 0; d < HEAD_DIM; d++) sv += qp[d] * kp[d];
        sv *= 0.125f;
        sc[h][m][n] = (m == n) ? 0.f : sv;
    }
    __syncwarp();

    if (l < NUM_SUBNETS) {
        float mx = -1e30f;
        #pragma unroll
        for (int n = 0; n < 8; n++) mx = fmaxf(mx, sc[h][l][n]);
        float e[8], sum = 0.f;
        #pragma unroll
        for (int n = 0; n < 8; n++) { e[n] = expf(sc[h][l][n] - mx); sum += e[n]; }
        float inv = 1.f / sum;
        #pragma unroll
        for (int n = 0; n < 8; n++) sc[h][l][n] = e[n] * inv;
    }
    __syncwarp();

    #pragma unroll
    for (int dd = 0; dd < 2; dd++) {
        int d = l + dd * 32;
        float vv[8];
        #pragma unroll
        for (int n = 0; n < 8; n++)
            vv[n] = __half2float(g_v[((size_t)(n * BATCH + b)) * HIDDEN + h * HEAD_DIM + d]);
        #pragma unroll
        for (int m = 0; m < 8; m++) {
            float cv = 0.f;
            #pragma unroll
            for (int n = 0; n < 8; n++) cv += sc[h][m][n] * vv[n];
            g_ctx[((size_t)(m * BATCH + b)) * HIDDEN + h * HEAD_DIM + d] = __float2half_rn(cv);
        }
    }
}

// ---------------- launch ----------------
extern "C" void kernel_launch(void* const* d_in, const int* in_sizes, int n_in,
                              void* d_out, int out_size)
{
    (void)in_sizes; (void)n_in; (void)out_size;
    const float* x    = (const float*)d_in[0];
    const float* W1   = (const float*)d_in[2];
    const float* b1   = (const float*)d_in[3];
    const float* W2   = (const float*)d_in[4];
    const float* b2   = (const float*)d_in[5];
    const float* ln_g = (const float*)d_in[6];
    const float* ln_b = (const float*)d_in[7];
    const float* Wq   = (const float*)d_in[8];
    const float* bq   = (const float*)d_in[9];
    const float* Wk   = (const float*)d_in[10];
    const float* bk   = (const float*)d_in[11];
    const float* Wv   = (const float*)d_in[12];
    const float* bv   = (const float*)d_in[13];
    const float* Wo   = (const float*)d_in[14];
    const float* bo   = (const float*)d_in[15];
    const float* Wp   = (const float*)d_in[16];
    const float* bp   = (const float*)d_in[17];
    float* out = (float*)d_out;

    __half *flat, *W1T_hi, *W2T_hi, *WqkvT_hi, *WoT_hi, *WpT_hi;
    __half *h, *xn, *ctx, *t, *pq, *pk, *pv;
    float *xsub;
    cudaGetSymbolAddress((void**)&flat,    g_flat);
    cudaGetSymbolAddress((void**)&W1T_hi,  g_W1T_hi);
    cudaGetSymbolAddress((void**)&W2T_hi,  g_W2T_hi);
    cudaGetSymbolAddress((void**)&WqkvT_hi, g_WqkvT_hi);
    cudaGetSymbolAddress((void**)&WoT_hi,  g_WoT_hi);
    cudaGetSymbolAddress((void**)&WpT_hi,  g_WpT_hi);
    cudaGetSymbolAddress((void**)&h,       g_h);
    cudaGetSymbolAddress((void**)&xn,      g_xn);
    cudaGetSymbolAddress((void**)&ctx,     g_ctx);
    cudaGetSymbolAddress((void**)&t,       g_t);
    cudaGetSymbolAddress((void**)&xsub,    g_xsub);
    cudaGetSymbolAddress((void**)&pq,      g_q);
    cudaGetSymbolAddress((void**)&pk,      g_k);
    cudaGetSymbolAddress((void**)&pv,      g_v);

    const int SMEM1 = 4 * 2 * T_BYTES;    // 73728, 2 CTAs/SM
    cudaFuncSetAttribute((const void*)tc_gemm<0>, cudaFuncAttributeMaxDynamicSharedMemorySize, SMEM1);
    cudaFuncSetAttribute((const void*)tc_gemm<1>, cudaFuncAttributeMaxDynamicSharedMemorySize, SMEM1);
    cudaFuncSetAttribute((const void*)tc_gemm<2>, cudaFuncAttributeMaxDynamicSharedMemorySize, SMEM1);
    cudaFuncSetAttribute((const void*)tc_gemm<3>, cudaFuncAttributeMaxDynamicSharedMemorySize, SMEM1);
    cudaFuncSetAttribute((const void*)tc_gemm<4>, cudaFuncAttributeMaxDynamicSharedMemorySize, SMEM1);

    // ---- all input conversions in ONE launch ----
    W13 wa;
    for (int z = 0; z < 8; z++) {
        wa.src[z] = W2 + (size_t)z * HIDDEN * HIDDEN;
        wa.dhi[z] = W2T_hi + (size_t)z * HIDDEN * HIDDEN;
    }
    const float* srcs[5] = { Wq, Wk, Wv, Wo, Wp };
    __half* dhis[5] = { WqkvT_hi, WqkvT_hi + 512 * 512, WqkvT_hi + 1024 * 512, WoT_hi, WpT_hi };
    for (int z = 0; z < 5; z++) {
        wa.src[8 + z] = srcs[z];
        wa.dhi[8 + z] = dhis[z];
    }
    convert_all_kernel<<<NB_ALL, 256>>>(x, W1, wa);

    dim3 g512(HIDDEN / BN, ROWS / BM);        // 8 x 32 = 256 CTAs
    dim3 gqkv(3 * HIDDEN / BN, ROWS / BM);    // 24 x 32 = 768 CTAs

    // GEMM1: h = relu(flat @ W1 + b1) -> fp16
    tc_gemm<0><<<g512, 256, SMEM1>>>(flat, KPAD1, W1T_hi, KPAD1,
        (long)HIDDEN * KPAD1, KPAD1 / BK, b1, nullptr, h,
        nullptr, nullptr, nullptr, nullptr, nullptr, nullptr, nullptr);
    // GEMM2: xsub = h @ W2 + b2 (fp32 out)
    tc_gemm<1><<<g512, 256, SMEM1>>>(h, HIDDEN, W2T_hi, HIDDEN,
        (long)HIDDEN * HIDDEN, HIDDEN / BK, b2, xsub, nullptr,
        nullptr, nullptr, nullptr, nullptr, nullptr, nullptr, nullptr);
    // LN -> xn fp16 (one warp per row)
    ln_kernel<<<ROWS / 8, 256>>>(ln_g, ln_b);
    // QKV fused (fp16 outputs, deep 4-stage pipeline, 2 CTAs/SM)
    tc_gemm<2><<<gqkv, 256, SMEM1>>>(xn, HIDDEN, WqkvT_hi, HIDDEN,
        0L, HIDDEN / BK, nullptr, nullptr, nullptr,
        nullptr, pq, pk, pv, bq, bk, bv);
    // attention -> ctx fp16
    attn_kernel<<<BATCH, 256>>>();
    // O: t = ctx @ Wo + bo -> fp16
    tc_gemm<3><<<g512, 256, SMEM1>>>(ctx, HIDDEN, WoT_hi, HIDDEN,
        0L, HIDDEN / BK, bo, nullptr, t,
        nullptr, nullptr, nullptr, nullptr, nullptr, nullptr, nullptr);
    // P: out = t @ Wp + bp + xsub (permuted to (b,s))
    tc_gemm<4><<<g512, 256, SMEM1>>>(t, HIDDEN, WpT_hi, HIDDEN,
        0L, HIDDEN / BK, bp, out, nullptr,
        xsub, nullptr, nullptr, nullptr, nullptr, nullptr, nullptr);
}